// round 5
// baseline (speedup 1.0000x reference)
#include <cuda_runtime.h>

#define BB 8
#define LL 512
#define KK 512
#define MM 64
#define NN 64
#define PDIM 64
#define DD 64

// scratch (device globals; no allocations)
__device__ float g_ssT [BB * KK * LL];        // 8 MB  exp(scores) stored [b][k][l]
__device__ float g_sum4[BB * 4 * LL];         // 64 KB per-(b,ktile) partial row sums
__device__ float g_vkc [BB * KK * NN];        // 1 MB
__device__ float g_tmp4[BB * 4 * LL * NN];    // 4 MB  split-K partial tmp

#define KB_STRIDE 68   // kbuf row stride (64 + 4)
#define QT_STRIDE 68   // qT row stride

__device__ __forceinline__ float4 f4add(float4 a, float4 b) {
    return make_float4(a.x + b.x, a.y + b.y, a.z + b.z, a.w + b.w);
}

// ============ Kernel A: block-specialized [scores^T+exp+sums | vkc] ============
__global__ void __launch_bounds__(256) ka_kernel(
    const float* __restrict__ q, const float* __restrict__ k,
    const float* __restrict__ vk, const float* __restrict__ vexp,
    const float* __restrict__ scale_p) {
    extern __shared__ float s[];
    int t = threadIdx.x;
    int bid = blockIdx.x;

    if (bid < 256) {
        float* kbuf = s;                        // [128][KB_STRIDE]
        float* qT   = s + 128 * KB_STRIDE;      // [64][QT_STRIDE]
        float* ssum = qT + 64 * QT_STRIDE;      // [64]
        int b  = bid >> 5;
        int r  = bid & 31;
        int l0 = (r >> 2) * 64;
        int kt = r & 3;
        int k0 = kt * 128;

        // load k tile [128][64] coalesced
#pragma unroll
        for (int j = 0; j < 8; j++) {
            int v = t + j * 256;
            int row = v >> 4, c4 = v & 15;
            float4 x = *(const float4*)&k[((size_t)(b * KK + k0 + row)) * DD + c4 * 4];
            *(float4*)&kbuf[row * KB_STRIDE + c4 * 4] = x;
        }
        // transpose q tile 64x64 -> qT[d][l]
#pragma unroll
        for (int i = 0; i < 4; i++) {
            int l = (t >> 4) + 16 * i;
            int d4 = t & 15;
            float4 x = *(const float4*)&q[((size_t)(b * LL + l0 + l)) * DD + d4 * 4];
            qT[(d4 * 4 + 0) * QT_STRIDE + l] = x.x;
            qT[(d4 * 4 + 1) * QT_STRIDE + l] = x.y;
            qT[(d4 * 4 + 2) * QT_STRIDE + l] = x.z;
            qT[(d4 * 4 + 3) * QT_STRIDE + l] = x.w;
        }
        if (t < 64) ssum[t] = 0.f;
        __syncthreads();

        int tkg = t >> 3;          // k rows tkg*4..+3
        int tlg = t & 7;           // l groups
        float acc[4][8];
#pragma unroll
        for (int a = 0; a < 4; a++)
#pragma unroll
            for (int b2 = 0; b2 < 8; b2++) acc[a][b2] = 0.f;

#pragma unroll 2
        for (int d0 = 0; d0 < DD; d0 += 4) {
            float4 kv[4];
#pragma unroll
            for (int ki = 0; ki < 4; ki++)
                kv[ki] = *(float4*)&kbuf[(tkg * 4 + ki) * KB_STRIDE + d0];
#pragma unroll
            for (int dd = 0; dd < 4; dd++) {
                float4 qa = *(float4*)&qT[(d0 + dd) * QT_STRIDE + tlg * 4];
                float4 qb = *(float4*)&qT[(d0 + dd) * QT_STRIDE + 32 + tlg * 4];
                float kd[4];
                kd[0] = ((float*)&kv[0])[dd];
                kd[1] = ((float*)&kv[1])[dd];
                kd[2] = ((float*)&kv[2])[dd];
                kd[3] = ((float*)&kv[3])[dd];
#pragma unroll
                for (int ki = 0; ki < 4; ki++) {
                    acc[ki][0] += kd[ki] * qa.x;
                    acc[ki][1] += kd[ki] * qa.y;
                    acc[ki][2] += kd[ki] * qa.z;
                    acc[ki][3] += kd[ki] * qa.w;
                    acc[ki][4] += kd[ki] * qb.x;
                    acc[ki][5] += kd[ki] * qb.y;
                    acc[ki][6] += kd[ki] * qb.z;
                    acc[ki][7] += kd[ki] * qb.w;
                }
            }
        }

        float scale = *scale_p;
        float sacc[8];
#pragma unroll
        for (int j = 0; j < 8; j++) sacc[j] = 0.f;
#pragma unroll
        for (int ki = 0; ki < 4; ki++) {
            float4 e0, e1;
            e0.x = __expf(acc[ki][0] * scale);
            e0.y = __expf(acc[ki][1] * scale);
            e0.z = __expf(acc[ki][2] * scale);
            e0.w = __expf(acc[ki][3] * scale);
            e1.x = __expf(acc[ki][4] * scale);
            e1.y = __expf(acc[ki][5] * scale);
            e1.z = __expf(acc[ki][6] * scale);
            e1.w = __expf(acc[ki][7] * scale);
            sacc[0] += e0.x; sacc[1] += e0.y; sacc[2] += e0.z; sacc[3] += e0.w;
            sacc[4] += e1.x; sacc[5] += e1.y; sacc[6] += e1.z; sacc[7] += e1.w;
            size_t base = ((size_t)(b * KK + k0 + tkg * 4 + ki)) * LL + l0;
            *(float4*)&g_ssT[base + tlg * 4]      = e0;
            *(float4*)&g_ssT[base + 32 + tlg * 4] = e1;
        }
#pragma unroll
        for (int j = 0; j < 4; j++) atomicAdd(&ssum[tlg * 4 + j], sacc[j]);
#pragma unroll
        for (int j = 0; j < 4; j++) atomicAdd(&ssum[32 + tlg * 4 + j], sacc[4 + j]);
        __syncthreads();
        if (t < 64) g_sum4[((size_t)(b * 4 + kt)) * LL + l0 + t] = ssum[t];
    } else {
        // ---- vkc blocks: 2 bk slabs, float4 loads, deep MLP, no mid-sync ----
        float4* r4 = (float4*)s;                // [2][256]
        int idx = bid - 256;                    // 0..2047
        int n4 = t & 15;                        // float4 column
        int pg = t >> 4;                        // 16 p-groups of 4
        float4 acc0 = make_float4(0.f, 0.f, 0.f, 0.f);
        float4 acc1 = acc0;
        const float* vk0 = vk + (size_t)(idx * 2) * PDIM * NN;
        const float* ve0 = vexp + (size_t)(idx * 2) * PDIM;
#pragma unroll
        for (int i = 0; i < 4; i++) {
            int p = pg * 4 + i;
            float4 a  = *(const float4*)&vk0[p * NN + n4 * 4];
            float4 b2 = *(const float4*)&vk0[PDIM * NN + p * NN + n4 * 4];
            float ea = ve0[p];
            float eb = ve0[PDIM + p];
            acc0.x += a.x * ea;  acc0.y += a.y * ea;  acc0.z += a.z * ea;  acc0.w += a.w * ea;
            acc1.x += b2.x * eb; acc1.y += b2.y * eb; acc1.z += b2.z * eb; acc1.w += b2.w * eb;
        }
        r4[t] = acc0;
        r4[256 + t] = acc1;
        __syncthreads();
        if (t < 128) {                          // fold pg 16 -> 4
            int slab = t >> 6, j = t & 63;
            float4* rr = &r4[slab * 256];
            rr[j] = f4add(f4add(rr[j], rr[j + 64]), f4add(rr[j + 128], rr[j + 192]));
        }
        __syncthreads();
        if (t < 32) {                           // fold 4 -> 1, write
            int slab = t >> 4, nn = t & 15;
            float4* rr = &r4[slab * 256];
            float4 o = f4add(f4add(rr[nn], rr[nn + 16]), f4add(rr[nn + 32], rr[nn + 48]));
            *(float4*)&g_vkc[(size_t)(idx * 2 + slab) * NN + nn * 4] = o;
        }
    }
}

// ============ K2: tmp4 = E^T(chunk) outer-product vkc(chunk), split-K ============
#define ES 68
#define VS 68
__global__ void __launch_bounds__(256) k2_kernel() {
    extern __shared__ float s[];
    float* Es = s;                 // [128][ES]  E^T chunk: [k][l]
    float* Vs = s + 128 * ES;      // [128][VS]  vkc chunk: [k][n]
    int t = threadIdx.x;
    int bid = blockIdx.x;
    int b  = bid >> 5;
    int r  = bid & 31;
    int l0 = (r >> 2) * 64;
    int ks = r & 3;
    int k0 = ks * 128;

#pragma unroll
    for (int j = 0; j < 8; j++) {
        int v = t + j * 256;
        int row = v >> 4, c4 = v & 15;
        float4 x = *(const float4*)&g_ssT[((size_t)(b * KK + k0 + row)) * LL + l0 + c4 * 4];
        *(float4*)&Es[row * ES + c4 * 4] = x;
    }
#pragma unroll
    for (int j = 0; j < 8; j++) {
        int v = t + j * 256;
        int row = v >> 4, c4 = v & 15;
        float4 x = *(const float4*)&g_vkc[((size_t)(b * KK + k0 + row)) * NN + c4 * 4];
        *(float4*)&Vs[row * VS + c4 * 4] = x;
    }
    __syncthreads();

    int tn = t >> 4, tl = t & 15;   // 4l x 4n per thread
    float acc[4][4];
#pragma unroll
    for (int a = 0; a < 4; a++)
#pragma unroll
        for (int b2 = 0; b2 < 4; b2++) acc[a][b2] = 0.f;
#pragma unroll 4
    for (int kk = 0; kk < 128; kk++) {
        float4 e4 = *(float4*)&Es[kk * ES + tl * 4];
        float4 v4 = *(float4*)&Vs[kk * VS + tn * 4];
        float ee[4] = {e4.x, e4.y, e4.z, e4.w};
        float vv[4] = {v4.x, v4.y, v4.z, v4.w};
#pragma unroll
        for (int li = 0; li < 4; li++)
#pragma unroll
            for (int nj = 0; nj < 4; nj++)
                acc[li][nj] += ee[li] * vv[nj];
    }
#pragma unroll
    for (int li = 0; li < 4; li++) {
        int l = l0 + tl * 4 + li;
        float4 o = {acc[li][0], acc[li][1], acc[li][2], acc[li][3]};
        *(float4*)&g_tmp4[(((size_t)(b * 4 + ks)) * LL + l) * NN + tn * 4] = o;
    }
}

// ============ K3: attn = vq @ tmp (normalized), residual + LayerNorm ============
__global__ void __launch_bounds__(256) k3_kernel(
    const float* __restrict__ q, const float* __restrict__ vq,
    const float* __restrict__ gamma, const float* __restrict__ beta,
    float* __restrict__ out) {
    int bl = blockIdx.x;             // b*512 + l
    int b = bl >> 9, l = bl & 511;
    __shared__ __align__(16) float stmp[64];
    __shared__ float sq[64];
    __shared__ float so[64];
    __shared__ float rs[8], rq[8];
    int t = threadIdx.x;
    if (t < 64) {
        float ssum = g_sum4[((size_t)(b * 4 + 0)) * LL + l] + g_sum4[((size_t)(b * 4 + 1)) * LL + l]
                   + g_sum4[((size_t)(b * 4 + 2)) * LL + l] + g_sum4[((size_t)(b * 4 + 3)) * LL + l];
        float inv = 1.f / ssum;
        float v = g_tmp4[(((size_t)(b * 4 + 0)) * LL + l) * NN + t]
                + g_tmp4[(((size_t)(b * 4 + 1)) * LL + l) * NN + t]
                + g_tmp4[(((size_t)(b * 4 + 2)) * LL + l) * NN + t]
                + g_tmp4[(((size_t)(b * 4 + 3)) * LL + l) * NN + t];
        stmp[t] = v * inv;
        sq[t]   = q[(size_t)bl * DD + t];
    }
    __syncthreads();

    int n4 = t & 15;
    float4 tm = ((float4*)stmp)[n4];
    const float4* vq4 = (const float4*)(vq + (size_t)bl * MM * NN);
    float p[4];
#pragma unroll
    for (int i = 0; i < 4; i++) {
        float4 v = vq4[t + i * 256];         // m = (t>>4) + 16*i, n-chunk = n4
        p[i] = v.x * tm.x + v.y * tm.y + v.z * tm.z + v.w * tm.w;
    }
#pragma unroll
    for (int o = 8; o; o >>= 1)
#pragma unroll
        for (int i = 0; i < 4; i++)
            p[i] += __shfl_down_sync(0xFFFFFFFFu, p[i], o, 16);
    if ((t & 15) == 0) {
        int g = t >> 4;
#pragma unroll
        for (int i = 0; i < 4; i++) so[g + 16 * i] = p[i];
    }
    __syncthreads();

    int m = t & 63;
    float x = sq[m] + so[m];                 // residual (M == D)
    float s1 = x, s2 = x * x;
#pragma unroll
    for (int o = 16; o; o >>= 1) {
        s1 += __shfl_xor_sync(0xFFFFFFFFu, s1, o);
        s2 += __shfl_xor_sync(0xFFFFFFFFu, s2, o);
    }
    int lane = t & 31, w = t >> 5;
    if (lane == 0) { rs[w] = s1; rq[w] = s2; }
    __syncthreads();
    float a = 0.f, b2 = 0.f;
#pragma unroll
    for (int i = 0; i < 8; i++) { a += rs[i]; b2 += rq[i]; }
    float mu   = a * (1.f / 256.f);          // each m replicated 4x -> exact mean
    float var  = b2 * (1.f / 256.f) - mu * mu;
    float rstd = rsqrtf(var + 1e-3f);
    if (t < 64)
        out[(size_t)bl * MM + m] = (x - mu) * rstd * gamma[m] + beta[m];
}

extern "C" void kernel_launch(void* const* d_in, const int* in_sizes, int n_in,
                              void* d_out, int out_size) {
    const float* q     = (const float*)d_in[0];
    const float* k     = (const float*)d_in[1];
    const float* vq    = (const float*)d_in[2];
    const float* vk    = (const float*)d_in[3];
    const float* vexp  = (const float*)d_in[4];
    const float* scale = (const float*)d_in[5];
    const float* gamma = (const float*)d_in[6];
    const float* beta  = (const float*)d_in[7];
    float* out = (float*)d_out;

    int smemA = (128 * KB_STRIDE + 64 * QT_STRIDE + 64) * (int)sizeof(float);
    cudaFuncSetAttribute(ka_kernel, cudaFuncAttributeMaxDynamicSharedMemorySize, smemA);
    ka_kernel<<<256 + 2048, 256, smemA>>>(q, k, vk, vexp, scale);

    int smem2 = (128 * ES + 128 * VS) * (int)sizeof(float);
    cudaFuncSetAttribute(k2_kernel, cudaFuncAttributeMaxDynamicSharedMemorySize, smem2);
    k2_kernel<<<256, 256, smem2>>>();

    k3_kernel<<<BB * LL, 256>>>(q, vq, gamma, beta, out);
}

// round 6
// speedup vs baseline: 1.2714x; 1.2714x over previous
#include <cuda_runtime.h>

#define BB 8
#define LL 512
#define KK 512
#define MM 64
#define NN 64
#define PDIM 64
#define DD 64

// scratch (device globals; no allocations)
__device__ float g_ssT [BB * KK * LL];        // 8 MB  exp(scores) stored [b][k][l]
__device__ float g_sum8[BB * 8 * LL];         // 128 KB per-(b,ktile) partial row sums
__device__ float g_vkc [BB * KK * NN];        // 1 MB
__device__ float g_tmp4[BB * 4 * LL * NN];    // 4 MB  split-K partial tmp

#define KB_STRIDE 68   // kbuf row stride (64 + 4)
#define QT_STRIDE 68   // qT row stride
#define NSCORE 512     // score blocks

// ============ Kernel A: block-specialized [scores^T+exp+sums | vkc] ============
// score block: 64k x 64l tile, thread tile 4k x 4l (low regs -> high occupancy)
__global__ void __launch_bounds__(256) ka_kernel(
    const float* __restrict__ q, const float* __restrict__ k,
    const float* __restrict__ vk, const float* __restrict__ vexp,
    const float* __restrict__ scale_p) {
    extern __shared__ float s[];
    int t = threadIdx.x;
    int bid = blockIdx.x;

    if (bid < NSCORE) {
        float* kbuf = s;                        // [64][KB_STRIDE]
        float* qT   = s + 64 * KB_STRIDE;       // [64][QT_STRIDE]
        float* ssum = qT + 64 * QT_STRIDE;      // [64]
        int b  = bid >> 6;
        int r  = bid & 63;
        int l0 = (r >> 3) * 64;
        int kt = r & 7;
        int k0 = kt * 64;

        // load k tile [64][64] coalesced (1024 float4)
#pragma unroll
        for (int j = 0; j < 4; j++) {
            int v = t + j * 256;
            int row = v >> 4, c4 = v & 15;
            float4 x = *(const float4*)&k[((size_t)(b * KK + k0 + row)) * DD + c4 * 4];
            *(float4*)&kbuf[row * KB_STRIDE + c4 * 4] = x;
        }
        // transpose q tile 64x64 -> qT[d][l]
#pragma unroll
        for (int i = 0; i < 4; i++) {
            int l = (t >> 4) + 16 * i;
            int d4 = t & 15;
            float4 x = *(const float4*)&q[((size_t)(b * LL + l0 + l)) * DD + d4 * 4];
            qT[(d4 * 4 + 0) * QT_STRIDE + l] = x.x;
            qT[(d4 * 4 + 1) * QT_STRIDE + l] = x.y;
            qT[(d4 * 4 + 2) * QT_STRIDE + l] = x.z;
            qT[(d4 * 4 + 3) * QT_STRIDE + l] = x.w;
        }
        if (t < 64) ssum[t] = 0.f;
        __syncthreads();

        int tkg = t >> 4;          // 16 k-groups of 4
        int tlg = t & 15;          // 16 l-groups of 4
        float acc[4][4];
#pragma unroll
        for (int a = 0; a < 4; a++)
#pragma unroll
            for (int b2 = 0; b2 < 4; b2++) acc[a][b2] = 0.f;

#pragma unroll 2
        for (int d0 = 0; d0 < DD; d0 += 4) {
            float4 kv[4];
#pragma unroll
            for (int ki = 0; ki < 4; ki++)
                kv[ki] = *(float4*)&kbuf[(tkg * 4 + ki) * KB_STRIDE + d0];
#pragma unroll
            for (int dd = 0; dd < 4; dd++) {
                float4 qa = *(float4*)&qT[(d0 + dd) * QT_STRIDE + tlg * 4];
                float kd0 = ((float*)&kv[0])[dd];
                float kd1 = ((float*)&kv[1])[dd];
                float kd2 = ((float*)&kv[2])[dd];
                float kd3 = ((float*)&kv[3])[dd];
                acc[0][0] += kd0 * qa.x; acc[0][1] += kd0 * qa.y; acc[0][2] += kd0 * qa.z; acc[0][3] += kd0 * qa.w;
                acc[1][0] += kd1 * qa.x; acc[1][1] += kd1 * qa.y; acc[1][2] += kd1 * qa.z; acc[1][3] += kd1 * qa.w;
                acc[2][0] += kd2 * qa.x; acc[2][1] += kd2 * qa.y; acc[2][2] += kd2 * qa.z; acc[2][3] += kd2 * qa.w;
                acc[3][0] += kd3 * qa.x; acc[3][1] += kd3 * qa.y; acc[3][2] += kd3 * qa.z; acc[3][3] += kd3 * qa.w;
            }
        }

        float scale = *scale_p;
        float sacc[4] = {0.f, 0.f, 0.f, 0.f};
#pragma unroll
        for (int ki = 0; ki < 4; ki++) {
            float4 e0;
            e0.x = __expf(acc[ki][0] * scale);
            e0.y = __expf(acc[ki][1] * scale);
            e0.z = __expf(acc[ki][2] * scale);
            e0.w = __expf(acc[ki][3] * scale);
            sacc[0] += e0.x; sacc[1] += e0.y; sacc[2] += e0.z; sacc[3] += e0.w;
            *(float4*)&g_ssT[((size_t)(b * KK + k0 + tkg * 4 + ki)) * LL + l0 + tlg * 4] = e0;
        }
#pragma unroll
        for (int j = 0; j < 4; j++) atomicAdd(&ssum[tlg * 4 + j], sacc[j]);
        __syncthreads();
        if (t < 64) g_sum8[((size_t)(b * 8 + kt)) * LL + l0 + t] = ssum[t];
    } else {
        // ---- vkc block: one bk slab, scalar loads (proven fast path) ----
        int bk = bid - NSCORE;                  // 0..4095
        const float* vkp = vk + (size_t)bk * PDIM * NN;
        const float* ve  = vexp + (size_t)bk * PDIM;
        int n = t & 63, pg = t >> 6;            // 4 p-groups of 16
        float acc = 0.f;
#pragma unroll
        for (int i = 0; i < 16; i++) {
            int p = pg * 16 + i;
            acc += vkp[p * NN + n] * ve[p];
        }
        s[t] = acc;
        __syncthreads();
        if (pg == 0)
            g_vkc[(size_t)bk * NN + n] = s[n] + s[64 + n] + s[128 + n] + s[192 + n];
    }
}

// ============ K2: tmp4 = E^T(chunk) outer-product vkc(chunk), split-K ============
#define ES 68
#define VS 68
__global__ void __launch_bounds__(256) k2_kernel() {
    extern __shared__ float s[];
    float* Es = s;                 // [128][ES]  E^T chunk: [k][l]
    float* Vs = s + 128 * ES;      // [128][VS]  vkc chunk: [k][n]
    int t = threadIdx.x;
    int bid = blockIdx.x;
    int b  = bid >> 5;
    int r  = bid & 31;
    int l0 = (r >> 2) * 64;
    int ks = r & 3;
    int k0 = ks * 128;

#pragma unroll
    for (int j = 0; j < 8; j++) {
        int v = t + j * 256;
        int row = v >> 4, c4 = v & 15;
        float4 x = *(const float4*)&g_ssT[((size_t)(b * KK + k0 + row)) * LL + l0 + c4 * 4];
        *(float4*)&Es[row * ES + c4 * 4] = x;
    }
#pragma unroll
    for (int j = 0; j < 8; j++) {
        int v = t + j * 256;
        int row = v >> 4, c4 = v & 15;
        float4 x = *(const float4*)&g_vkc[((size_t)(b * KK + k0 + row)) * NN + c4 * 4];
        *(float4*)&Vs[row * VS + c4 * 4] = x;
    }
    __syncthreads();

    int tn = t >> 4, tl = t & 15;   // 4l x 4n per thread
    float acc[4][4];
#pragma unroll
    for (int a = 0; a < 4; a++)
#pragma unroll
        for (int b2 = 0; b2 < 4; b2++) acc[a][b2] = 0.f;
#pragma unroll 4
    for (int kk = 0; kk < 128; kk++) {
        float4 e4 = *(float4*)&Es[kk * ES + tl * 4];
        float4 v4 = *(float4*)&Vs[kk * VS + tn * 4];
        float ee[4] = {e4.x, e4.y, e4.z, e4.w};
        float vv[4] = {v4.x, v4.y, v4.z, v4.w};
#pragma unroll
        for (int li = 0; li < 4; li++)
#pragma unroll
            for (int nj = 0; nj < 4; nj++)
                acc[li][nj] += ee[li] * vv[nj];
    }
#pragma unroll
    for (int li = 0; li < 4; li++) {
        int l = l0 + tl * 4 + li;
        float4 o = {acc[li][0], acc[li][1], acc[li][2], acc[li][3]};
        *(float4*)&g_tmp4[(((size_t)(b * 4 + ks)) * LL + l) * NN + tn * 4] = o;
    }
}

// ============ K3: attn = vq @ tmp (normalized), residual + LayerNorm ============
__global__ void __launch_bounds__(256) k3_kernel(
    const float* __restrict__ q, const float* __restrict__ vq,
    const float* __restrict__ gamma, const float* __restrict__ beta,
    float* __restrict__ out) {
    int bl = blockIdx.x;             // b*512 + l
    int b = bl >> 9, l = bl & 511;
    __shared__ __align__(16) float stmp[64];
    __shared__ float sq[64];
    __shared__ float so[64];
    __shared__ float rs[8], rq[8];
    int t = threadIdx.x;
    if (t < 64) {
        float ssum = 0.f;
#pragma unroll
        for (int i = 0; i < 8; i++) ssum += g_sum8[((size_t)(b * 8 + i)) * LL + l];
        float inv = 1.f / ssum;
        float v = g_tmp4[(((size_t)(b * 4 + 0)) * LL + l) * NN + t]
                + g_tmp4[(((size_t)(b * 4 + 1)) * LL + l) * NN + t]
                + g_tmp4[(((size_t)(b * 4 + 2)) * LL + l) * NN + t]
                + g_tmp4[(((size_t)(b * 4 + 3)) * LL + l) * NN + t];
        stmp[t] = v * inv;
        sq[t]   = q[(size_t)bl * DD + t];
    }
    __syncthreads();

    int n4 = t & 15;
    float4 tm = ((float4*)stmp)[n4];
    const float4* vq4 = (const float4*)(vq + (size_t)bl * MM * NN);
    float p[4];
#pragma unroll
    for (int i = 0; i < 4; i++) {
        float4 v = vq4[t + i * 256];         // m = (t>>4) + 16*i, n-chunk = n4
        p[i] = v.x * tm.x + v.y * tm.y + v.z * tm.z + v.w * tm.w;
    }
#pragma unroll
    for (int o = 8; o; o >>= 1)
#pragma unroll
        for (int i = 0; i < 4; i++)
            p[i] += __shfl_down_sync(0xFFFFFFFFu, p[i], o, 16);
    if ((t & 15) == 0) {
        int g = t >> 4;
#pragma unroll
        for (int i = 0; i < 4; i++) so[g + 16 * i] = p[i];
    }
    __syncthreads();

    int m = t & 63;
    float x = sq[m] + so[m];                 // residual (M == D)
    float s1 = x, s2 = x * x;
#pragma unroll
    for (int o = 16; o; o >>= 1) {
        s1 += __shfl_xor_sync(0xFFFFFFFFu, s1, o);
        s2 += __shfl_xor_sync(0xFFFFFFFFu, s2, o);
    }
    int lane = t & 31, w = t >> 5;
    if (lane == 0) { rs[w] = s1; rq[w] = s2; }
    __syncthreads();
    float a = 0.f, b2 = 0.f;
#pragma unroll
    for (int i = 0; i < 8; i++) { a += rs[i]; b2 += rq[i]; }
    float mu   = a * (1.f / 256.f);          // each m replicated 4x -> exact mean
    float var  = b2 * (1.f / 256.f) - mu * mu;
    float rstd = rsqrtf(var + 1e-3f);
    if (t < 64)
        out[(size_t)bl * MM + m] = (x - mu) * rstd * gamma[m] + beta[m];
}

extern "C" void kernel_launch(void* const* d_in, const int* in_sizes, int n_in,
                              void* d_out, int out_size) {
    const float* q     = (const float*)d_in[0];
    const float* k     = (const float*)d_in[1];
    const float* vq    = (const float*)d_in[2];
    const float* vk    = (const float*)d_in[3];
    const float* vexp  = (const float*)d_in[4];
    const float* scale = (const float*)d_in[5];
    const float* gamma = (const float*)d_in[6];
    const float* beta  = (const float*)d_in[7];
    float* out = (float*)d_out;

    int smemA = (64 * KB_STRIDE + 64 * QT_STRIDE + 64) * (int)sizeof(float);
    cudaFuncSetAttribute(ka_kernel, cudaFuncAttributeMaxDynamicSharedMemorySize, smemA);
    ka_kernel<<<NSCORE + BB * KK, 256, smemA>>>(q, k, vk, vexp, scale);

    int smem2 = (128 * ES + 128 * VS) * (int)sizeof(float);
    cudaFuncSetAttribute(k2_kernel, cudaFuncAttributeMaxDynamicSharedMemorySize, smem2);
    k2_kernel<<<256, 256, smem2>>>();

    k3_kernel<<<BB * LL, 256>>>(q, vq, gamma, beta, out);
}